// round 11
// baseline (speedup 1.0000x reference)
#include <cuda_runtime.h>
#include <cuda_fp16.h>
#include <cstdint>

#define NMAX 100000
#define DIM 128
#define NREL 8
#define AS 136   // padded smem row stride (halfs); 272B rows -> conflict-free LDSM

// Scratch (static device globals; runtime allocation is forbidden)
__device__ float g_h[(size_t)NMAX * DIM];             // layer-1 output (fp32)
__device__ __half g_Af[(size_t)NMAX * DIM];           // fp16 activations (layer input)
__device__ __half g_Wf[2 * 9 * DIM * DIM];            // fp16 transposed [bn][n][k] weights
// CSR sort structures (shared by both layers)
__device__ int g_cnt[NMAX * NREL];
__device__ int g_off[NMAX * NREL + 1];
__device__ int g_cursor[NMAX * NREL];
__device__ int g_bsum[1024];
__device__ int g_esrc[640000];

// ---------------------------------------------------------------------------
// fp16 conversions
// ---------------------------------------------------------------------------
__global__ void convert_half_kernel(const float* __restrict__ src, int nelem4, int do_relu) {
    int i = blockIdx.x * blockDim.x + threadIdx.x;
    if (i >= nelem4) return;
    float4 v = ((const float4*)src)[i];
    if (do_relu) {
        v.x = fmaxf(v.x, 0.f); v.y = fmaxf(v.y, 0.f);
        v.z = fmaxf(v.z, 0.f); v.w = fmaxf(v.w, 0.f);
    }
    __half2 h0 = __floats2half2_rn(v.x, v.y);
    __half2 h1 = __floats2half2_rn(v.z, v.w);
    uint2 packed = make_uint2(*reinterpret_cast<unsigned*>(&h0),
                              *reinterpret_cast<unsigned*>(&h1));
    ((uint2*)g_Af)[i] = packed;
}

// weights [k][n] fp32 -> transposed [bn][n][k] fp16
__global__ void wconvert_kernel(const float* __restrict__ root,
                                const float* __restrict__ rel,
                                __half* __restrict__ wf) {
    int i = blockIdx.x * blockDim.x + threadIdx.x;
    if (i >= 9 * DIM * DIM) return;
    int bn = i >> 14;
    int t  = i & 16383;
    int n  = t >> 7;
    int k  = t & 127;
    float w = bn ? rel[(size_t)(bn - 1) * DIM * DIM + k * DIM + n] : root[k * DIM + n];
    wf[i] = __float2half_rn(w);
}

// ---------------------------------------------------------------------------
// CSR build: histogram -> 2-level exclusive scan -> counting sort of src ids
// ---------------------------------------------------------------------------
__global__ void zero_cnt_kernel(int n8) {
    int i = blockIdx.x * blockDim.x + threadIdx.x;
    if (i < n8) g_cnt[i] = 0;
}

__global__ void hist_kernel(const int* __restrict__ ei,
                            const int* __restrict__ et, int e) {
    int i = blockIdx.x * blockDim.x + threadIdx.x;
    if (i >= e) return;
    atomicAdd(&g_cnt[ei[e + i] * NREL + et[i]], 1);
}

__global__ void scan1_kernel(int n8) {
    __shared__ int sm[256];
    int t = threadIdx.x;
    int base = blockIdx.x * 1024 + t * 4;
    int v0 = 0, v1 = 0, v2 = 0, v3 = 0;
    if (base + 0 < n8) v0 = g_cnt[base + 0];
    if (base + 1 < n8) v1 = g_cnt[base + 1];
    if (base + 2 < n8) v2 = g_cnt[base + 2];
    if (base + 3 < n8) v3 = g_cnt[base + 3];
    int tsum = v0 + v1 + v2 + v3;
    sm[t] = tsum;
    __syncthreads();
#pragma unroll
    for (int d = 1; d < 256; d <<= 1) {
        int x = (t >= d) ? sm[t - d] : 0;
        __syncthreads();
        sm[t] += x;
        __syncthreads();
    }
    int run = sm[t] - tsum;
    if (base + 0 < n8) { g_off[base + 0] = run; run += v0; }
    if (base + 1 < n8) { g_off[base + 1] = run; run += v1; }
    if (base + 2 < n8) { g_off[base + 2] = run; run += v2; }
    if (base + 3 < n8) { g_off[base + 3] = run; }
    if (t == 255) g_bsum[blockIdx.x] = sm[255];
}

__global__ void scan2_kernel(int nb) {
    __shared__ int sm[1024];
    int t = threadIdx.x;
    int v = (t < nb) ? g_bsum[t] : 0;
    sm[t] = v;
    __syncthreads();
#pragma unroll
    for (int d = 1; d < 1024; d <<= 1) {
        int x = (t >= d) ? sm[t - d] : 0;
        __syncthreads();
        sm[t] += x;
        __syncthreads();
    }
    if (t < nb) g_bsum[t] = sm[t] - v;
}

__global__ void scan3_kernel(int n8, int e) {
    int i = blockIdx.x * blockDim.x + threadIdx.x;
    if (i < n8) {
        int v = g_off[i] + g_bsum[i >> 10];
        g_off[i] = v;
        g_cursor[i] = v;
    }
    if (i == 0) g_off[n8] = e;
}

__global__ void sort_edges_kernel(const int* __restrict__ ei,
                                  const int* __restrict__ et, int e) {
    int i = blockIdx.x * blockDim.x + threadIdx.x;
    if (i >= e) return;
    int bin = ei[e + i] * NREL + et[i];
    int pos = atomicAdd(&g_cursor[bin], 1);
    g_esrc[pos] = ei[i];
}

// ---------------------------------------------------------------------------
// Fused gather+GEMM (mma m16n8k16 fp16, fp32 accum):
//   out[128-row tile] = [x | mean_agg_1..8(x)] @ [root; W_1..W_8] + bias
//   Loops bn=0..8: stage A-chunk (bn=0 direct rows; bn>=1 CSR gather-mean of
//   L2-resident g_Af into SMEM), stage B-chunk = W_bn, 8 ks MMA steps into
//   persistent accumulators. Single fp32 epilogue. No Y buffer, no agg pass.
//   256 threads = 8 warps (4 wm x 2 wn), warp tile 32x64.
// ---------------------------------------------------------------------------
#define MMA16816(d, a, b)                                                  \
    asm volatile(                                                          \
        "mma.sync.aligned.m16n8k16.row.col.f32.f16.f16.f32 "               \
        "{%0,%1,%2,%3},{%4,%5,%6,%7},{%8,%9},{%0,%1,%2,%3};"               \
        : "+f"(d[0]), "+f"(d[1]), "+f"(d[2]), "+f"(d[3])                   \
        : "r"(a[0]), "r"(a[1]), "r"(a[2]), "r"(a[3]), "r"(b[0]), "r"(b[1]))

#define LDSM4(R, ADDR)                                                     \
    asm volatile("ldmatrix.sync.aligned.m8n8.x4.shared.b16 "               \
                 "{%0,%1,%2,%3}, [%4];"                                    \
                 : "=r"(R[0]), "=r"(R[1]), "=r"(R[2]), "=r"(R[3])          \
                 : "r"(ADDR))

__global__ __launch_bounds__(256) void gemm_fused_kernel(
    const __half* __restrict__ wf,   // layer base [9][128][128] (n,k)
    const float* __restrict__ bias,
    float* __restrict__ out, int nrows)
{
    extern __shared__ __half smem[];
    __half* sA = smem;                 // 128 x AS
    __half* sB = sA + 128 * AS;        // 128 x AS

    const int row0 = blockIdx.x * 128;
    const int tid  = threadIdx.x;
    const int lane = tid & 31;
    const int warp = tid >> 5;
    const int wm   = warp & 3;
    const int wn   = warp >> 2;
    const int grp  = lane >> 2;
    const int tg   = lane & 3;
    const int half = lane >> 4;       // staging: edge parity
    const int hl   = lane & 15;       // staging: 16B column group

    const unsigned sAB = (unsigned)__cvta_generic_to_shared(sA);
    const unsigned sBB = (unsigned)__cvta_generic_to_shared(sB);
    const unsigned aoff = (unsigned)(((wm * 32 + (lane & 15)) * AS +
                                      ((lane >> 4) << 3)) * 2);
    const unsigned boff = (unsigned)(((wn * 64 + ((lane >> 4) << 3) + (lane & 7)) * AS +
                                      (((lane >> 3) & 1) << 3)) * 2);

    float acc[2][8][4];
#pragma unroll
    for (int mi = 0; mi < 2; mi++)
#pragma unroll
        for (int ni = 0; ni < 8; ni++)
#pragma unroll
            for (int q = 0; q < 4; q++) acc[mi][ni][q] = 0.0f;

    for (int bn = 0; bn < 9; bn++) {
        if (bn > 0) __syncthreads();   // previous MMA phase done reading sA/sB

        // ---- stage B chunk = W_bn ----
        const __half* B = wf + (size_t)bn * DIM * DIM;
#pragma unroll
        for (int it = 0; it < 8; it++) {
            int id = tid + it * 256;
            int r  = id >> 4;
            int c  = id & 15;
            *(uint4*)(sB + r * AS + c * 8) = *(const uint4*)(B + (size_t)r * DIM + c * 8);
        }

        // ---- stage A chunk ----
        if (bn == 0) {
#pragma unroll
            for (int it = 0; it < 8; it++) {
                int id = tid + it * 256;
                int r  = id >> 4;
                int c  = id & 15;
                int gr = row0 + r;
                uint4 v = make_uint4(0, 0, 0, 0);
                if (gr < nrows)
                    v = *(const uint4*)(g_Af + (size_t)gr * DIM + c * 8);
                *(uint4*)(sA + r * AS + c * 8) = v;
            }
        } else {
            const int rr = bn - 1;
            // preload segment offsets for this warp's 16 rows:
            //   lanes 0-15 hold off[dst*8+rr], lanes 16-31 hold off[dst*8+rr+1]
            int dl = row0 + warp * 16 + hl;
            int offv = 0;
            if (dl < nrows) offv = g_off[dl * NREL + rr + half];
            for (int rowit = 0; rowit < 16; rowit++) {
                int s0 = __shfl_sync(0xffffffffu, offv, rowit);
                int s1 = __shfl_sync(0xffffffffu, offv, rowit + 16);
                float a[8];
#pragma unroll
                for (int j = 0; j < 8; j++) a[j] = 0.0f;
                for (int i = s0 + half; i < s1; i += 2) {
                    int src = g_esrc[i];
                    const uint4 v = *(const uint4*)(g_Af + (size_t)src * DIM + hl * 8);
                    const __half2* h2 = reinterpret_cast<const __half2*>(&v);
#pragma unroll
                    for (int j = 0; j < 4; j++) {
                        float2 f = __half22float2(h2[j]);
                        a[2 * j]     += f.x;
                        a[2 * j + 1] += f.y;
                    }
                }
#pragma unroll
                for (int j = 0; j < 8; j++)
                    a[j] += __shfl_xor_sync(0xffffffffu, a[j], 16);
                if (half == 0) {
                    float inv = (s1 > s0) ? 1.0f / (float)(s1 - s0) : 0.0f;
                    uint4 u;
                    __half2 h;
                    h = __floats2half2_rn(a[0] * inv, a[1] * inv);
                    u.x = *reinterpret_cast<unsigned*>(&h);
                    h = __floats2half2_rn(a[2] * inv, a[3] * inv);
                    u.y = *reinterpret_cast<unsigned*>(&h);
                    h = __floats2half2_rn(a[4] * inv, a[5] * inv);
                    u.z = *reinterpret_cast<unsigned*>(&h);
                    h = __floats2half2_rn(a[6] * inv, a[7] * inv);
                    u.w = *reinterpret_cast<unsigned*>(&h);
                    int row = warp * 16 + rowit;
                    *(uint4*)(sA + row * AS + hl * 8) = u;
                }
            }
        }
        __syncthreads();

        // ---- MMA phase: 8 k-steps of 16 ----
#pragma unroll
        for (int ks = 0; ks < 8; ks++) {
            const unsigned kb = ks * 32;
            unsigned a[2][4];
#pragma unroll
            for (int mi = 0; mi < 2; mi++)
                LDSM4(a[mi], sAB + aoff + mi * (16 * AS * 2) + kb);
            unsigned b[8][2];
#pragma unroll
            for (int p = 0; p < 4; p++) {
                unsigned t[4];
                LDSM4(t, sBB + boff + p * (16 * AS * 2) + kb);
                b[2 * p][0] = t[0]; b[2 * p][1] = t[1];
                b[2 * p + 1][0] = t[2]; b[2 * p + 1][1] = t[3];
            }
#pragma unroll
            for (int ni = 0; ni < 8; ni++)
#pragma unroll
                for (int mi = 0; mi < 2; mi++)
                    MMA16816(acc[mi][ni], a[mi], b[ni]);
        }
    }

    // ---- single epilogue: out = acc + bias (fp32) ----
#pragma unroll
    for (int mi = 0; mi < 2; mi++) {
        int r0 = row0 + wm * 32 + mi * 16 + grp;
#pragma unroll
        for (int ni = 0; ni < 8; ni++) {
            int col = wn * 64 + ni * 8 + 2 * tg;
            float b0 = bias[col], b1 = bias[col + 1];
            if (r0 < nrows) {
                float2 o = make_float2(acc[mi][ni][0] + b0, acc[mi][ni][1] + b1);
                *(float2*)&out[(size_t)r0 * DIM + col] = o;
            }
            if (r0 + 8 < nrows) {
                float2 o = make_float2(acc[mi][ni][2] + b0, acc[mi][ni][3] + b1);
                *(float2*)&out[(size_t)(r0 + 8) * DIM + col] = o;
            }
        }
    }
}

__global__ void relu_kernel(float* __restrict__ p, int n) {
    int i = blockIdx.x * blockDim.x + threadIdx.x;
    if (i < n) p[i] = fmaxf(p[i], 0.0f);
}

// ---------------------------------------------------------------------------
// Launch (CSR must precede the fused GEMM)
// ---------------------------------------------------------------------------
extern "C" void kernel_launch(void* const* d_in, const int* in_sizes, int n_in,
                              void* d_out, int out_size)
{
    const float* x   = (const float*)d_in[0];
    const int*   ei  = (const int*)d_in[1];  // [2,E] int32
    const int*   et  = (const int*)d_in[2];  // [E]   int32
    const float* rw1 = (const float*)d_in[3];
    const float* ro1 = (const float*)d_in[4];
    const float* b1  = (const float*)d_in[5];
    const float* rw2 = (const float*)d_in[6];
    const float* ro2 = (const float*)d_in[7];
    const float* b2  = (const float*)d_in[8];
    float* out = (float*)d_out;

    const int n = in_sizes[0] / DIM;
    const int e = in_sizes[2];

    float* hptr;
    cudaGetSymbolAddress((void**)&hptr, g_h);
    __half* wf;
    cudaGetSymbolAddress((void**)&wf, g_Wf);

    const int smem_bytes = 2 * 128 * AS * 2;   // 69632
    static bool attr_done = false;
    if (!attr_done) {
        cudaFuncSetAttribute(gemm_fused_kernel,
                             cudaFuncAttributeMaxDynamicSharedMemorySize, smem_bytes);
        attr_done = true;
    }

    const int n8 = n * NREL;
    const int nscan = (n8 + 1023) / 1024;
    const int mtiles = (n + 127) / 128;
    const int nw = 9 * DIM * DIM;

    // conversions
    wconvert_kernel<<<(nw + 255) / 256, 256>>>(ro1, rw1, wf);
    wconvert_kernel<<<(nw + 255) / 256, 256>>>(ro2, rw2, wf + nw);
    convert_half_kernel<<<(n * 32 + 255) / 256, 256>>>(x, n * 32, 0);

    // CSR build (shared by both layers)
    zero_cnt_kernel<<<(n8 + 255) / 256, 256>>>(n8);
    hist_kernel<<<(e + 255) / 256, 256>>>(ei, et, e);
    scan1_kernel<<<nscan, 256>>>(n8);
    scan2_kernel<<<1, 1024>>>(nscan);
    scan3_kernel<<<(n8 + 255) / 256, 256>>>(n8, e);
    sort_edges_kernel<<<(e + 255) / 256, 256>>>(ei, et, e);

    // layer 1: h = gemm_fused(x) ; relu fused into fp16 convert
    gemm_fused_kernel<<<mtiles, 256, smem_bytes>>>(wf, b1, hptr, n);
    convert_half_kernel<<<(n * 32 + 255) / 256, 256>>>(hptr, n * 32, 1);

    // layer 2: out = relu(gemm_fused(h))
    gemm_fused_kernel<<<mtiles, 256, smem_bytes>>>(wf + nw, b2, out, n);
    relu_kernel<<<(n * DIM + 255) / 256, 256>>>(out, n * DIM);
}

// round 12
// speedup vs baseline: 1.1644x; 1.1644x over previous
#include <cuda_runtime.h>
#include <cuda_fp16.h>
#include <cstdint>

#define NMAX 100000
#define DIM 128
#define NREL 8
#define AS 136   // padded smem row stride (halfs); 272B rows -> conflict-free LDSM

// Scratch (static device globals; runtime allocation is forbidden)
__device__ __half g_Yh[(size_t)NMAX * NREL * DIM];    // per-relation transformed feats (fp16)
__device__ float g_h[(size_t)NMAX * DIM];             // layer-1 root buffer (fp32)
__device__ __half g_Af[(size_t)NMAX * DIM];           // fp16 activations (layer input)
__device__ __half g_Wf[2 * 9 * DIM * DIM];            // fp16 transposed [bn][n][k] weights
// CSR sort structures (shared by both layers)
__device__ int g_cnt[NMAX * NREL];
__device__ int g_off[NMAX * NREL + 1];
__device__ int g_cursor[NMAX * NREL];
__device__ int g_bsum[1024];
__device__ int g_esrc[640000];

// ---------------------------------------------------------------------------
// fp16 conversions
// ---------------------------------------------------------------------------
__global__ void convert_half_kernel(const float* __restrict__ src, int nelem4) {
    int i = blockIdx.x * blockDim.x + threadIdx.x;
    if (i >= nelem4) return;
    float4 v = ((const float4*)src)[i];
    __half2 h0 = __floats2half2_rn(v.x, v.y);
    __half2 h1 = __floats2half2_rn(v.z, v.w);
    uint2 packed = make_uint2(*reinterpret_cast<unsigned*>(&h0),
                              *reinterpret_cast<unsigned*>(&h1));
    ((uint2*)g_Af)[i] = packed;
}

// weights [k][n] fp32 -> transposed [bn][n][k] fp16
__global__ void wconvert_kernel(const float* __restrict__ root,
                                const float* __restrict__ rel,
                                __half* __restrict__ wf) {
    int i = blockIdx.x * blockDim.x + threadIdx.x;
    if (i >= 9 * DIM * DIM) return;
    int bn = i >> 14;
    int t  = i & 16383;
    int n  = t >> 7;
    int k  = t & 127;
    float w = bn ? rel[(size_t)(bn - 1) * DIM * DIM + k * DIM + n] : root[k * DIM + n];
    wf[i] = __float2half_rn(w);
}

// ---------------------------------------------------------------------------
// CSR build: histogram -> 2-level exclusive scan -> counting sort of src ids
// ---------------------------------------------------------------------------
__global__ void zero_cnt_kernel(int n8v4) {
    int i = blockIdx.x * blockDim.x + threadIdx.x;
    if (i < n8v4) ((int4*)g_cnt)[i] = make_int4(0, 0, 0, 0);
}

__global__ void hist_kernel(const int* __restrict__ ei,
                            const int* __restrict__ et, int e) {
    int i = blockIdx.x * blockDim.x + threadIdx.x;
    if (i >= e) return;
    atomicAdd(&g_cnt[ei[e + i] * NREL + et[i]], 1);
}

__global__ void scan1_kernel(int n8) {
    __shared__ int sm[256];
    int t = threadIdx.x;
    int base = blockIdx.x * 1024 + t * 4;
    int v0 = 0, v1 = 0, v2 = 0, v3 = 0;
    if (base + 0 < n8) v0 = g_cnt[base + 0];
    if (base + 1 < n8) v1 = g_cnt[base + 1];
    if (base + 2 < n8) v2 = g_cnt[base + 2];
    if (base + 3 < n8) v3 = g_cnt[base + 3];
    int tsum = v0 + v1 + v2 + v3;
    sm[t] = tsum;
    __syncthreads();
#pragma unroll
    for (int d = 1; d < 256; d <<= 1) {
        int x = (t >= d) ? sm[t - d] : 0;
        __syncthreads();
        sm[t] += x;
        __syncthreads();
    }
    int run = sm[t] - tsum;
    if (base + 0 < n8) { g_off[base + 0] = run; run += v0; }
    if (base + 1 < n8) { g_off[base + 1] = run; run += v1; }
    if (base + 2 < n8) { g_off[base + 2] = run; run += v2; }
    if (base + 3 < n8) { g_off[base + 3] = run; }
    if (t == 255) g_bsum[blockIdx.x] = sm[255];
}

__global__ void scan2_kernel(int nb) {
    __shared__ int sm[1024];
    int t = threadIdx.x;
    int v = (t < nb) ? g_bsum[t] : 0;
    sm[t] = v;
    __syncthreads();
#pragma unroll
    for (int d = 1; d < 1024; d <<= 1) {
        int x = (t >= d) ? sm[t - d] : 0;
        __syncthreads();
        sm[t] += x;
        __syncthreads();
    }
    if (t < nb) g_bsum[t] = sm[t] - v;
}

__global__ void scan3_kernel(int n8, int e) {
    int i = blockIdx.x * blockDim.x + threadIdx.x;
    if (i < n8) {
        int v = g_off[i] + g_bsum[i >> 10];
        g_off[i] = v;
        g_cursor[i] = v;
    }
    if (i == 0) g_off[n8] = e;
}

__global__ void sort_edges_kernel(const int* __restrict__ ei,
                                  const int* __restrict__ et, int e) {
    int i = blockIdx.x * blockDim.x + threadIdx.x;
    if (i >= e) return;
    int bin = ei[e + i] * NREL + et[i];
    int pos = atomicAdd(&g_cursor[bin], 1);
    g_esrc[pos] = ei[i];
}

// ---------------------------------------------------------------------------
// Tensor-core GEMM, bn-loop-in-block (mma m16n8k16 fp16, fp32 accum):
//   One block per 128-row m-tile. A staged ONCE; loops bn=0..8 with B
//   double-buffered via cp.async (staging overlaps MMA).
//   256 threads = 8 warps (4 wm x 2 wn), warp tile 32x64.
//   bn==0 -> outroot fp32 + bias; bn>=1 -> g_Yh fp16.
// ---------------------------------------------------------------------------
#define MMA16816(d, a, b)                                                  \
    asm volatile(                                                          \
        "mma.sync.aligned.m16n8k16.row.col.f32.f16.f16.f32 "               \
        "{%0,%1,%2,%3},{%4,%5,%6,%7},{%8,%9},{%0,%1,%2,%3};"               \
        : "+f"(d[0]), "+f"(d[1]), "+f"(d[2]), "+f"(d[3])                   \
        : "r"(a[0]), "r"(a[1]), "r"(a[2]), "r"(a[3]), "r"(b[0]), "r"(b[1]))

#define LDSM4(R, ADDR)                                                     \
    asm volatile("ldmatrix.sync.aligned.m8n8.x4.shared.b16 "               \
                 "{%0,%1,%2,%3}, [%4];"                                    \
                 : "=r"(R[0]), "=r"(R[1]), "=r"(R[2]), "=r"(R[3])          \
                 : "r"(ADDR))

#define CP_ASYNC16(dst, src)                                               \
    asm volatile("cp.async.ca.shared.global [%0], [%1], 16;"               \
                 :: "r"(dst), "l"(src) : "memory")
#define CP_COMMIT()  asm volatile("cp.async.commit_group;" ::: "memory")
#define CP_WAIT0()   asm volatile("cp.async.wait_group 0;" ::: "memory")

__global__ __launch_bounds__(256) void gemm_bn_kernel(
    const __half* __restrict__ wf,   // layer base [9][128][128] (n,k)
    const float* __restrict__ bias,
    float* __restrict__ outroot, int nrows)
{
    extern __shared__ __half smem[];
    __half* sA = smem;                       // 128 x AS
    // two B buffers follow: sB0 at +128*AS, sB1 at +256*AS

    const int row0 = blockIdx.x * 128;
    const int tid  = threadIdx.x;
    const int lane = tid & 31;
    const int warp = tid >> 5;
    const int wm   = warp & 3;
    const int wn   = warp >> 2;
    const int grp  = lane >> 2;
    const int tg   = lane & 3;

    const unsigned sAB  = (unsigned)__cvta_generic_to_shared(sA);
    const unsigned sBB0 = sAB + 128 * AS * 2;
    const unsigned BSZ  = 128 * AS * 2;      // one B buffer in bytes

    const unsigned aoff = (unsigned)(((wm * 32 + (lane & 15)) * AS +
                                      ((lane >> 4) << 3)) * 2);
    const unsigned boff = (unsigned)(((wn * 64 + ((lane >> 4) << 3) + (lane & 7)) * AS +
                                      (((lane >> 3) & 1) << 3)) * 2);

    // ---- stage A once (cp.async; zero-fill OOB rows) + B(0) ----
#pragma unroll
    for (int it = 0; it < 8; it++) {
        int id = tid + it * 256;
        int r  = id >> 4;
        int c  = id & 15;
        int gr = row0 + r;
        unsigned dst = sAB + (unsigned)((r * AS + c * 8) * 2);
        if (gr < nrows) {
            CP_ASYNC16(dst, g_Af + (size_t)gr * DIM + c * 8);
        } else {
            asm volatile("st.shared.v4.b32 [%0], {%1,%1,%1,%1};"
                         :: "r"(dst), "r"(0u) : "memory");
        }
    }
#pragma unroll
    for (int it = 0; it < 8; it++) {
        int id = tid + it * 256;
        int r  = id >> 4;
        int c  = id & 15;
        CP_ASYNC16(sBB0 + (unsigned)((r * AS + c * 8) * 2),
                   wf + (size_t)r * DIM + c * 8);
    }
    CP_COMMIT();
    CP_WAIT0();
    __syncthreads();

    for (int bn = 0; bn < 9; bn++) {
        const unsigned bsel = sBB0 + (unsigned)(bn & 1) * BSZ;

        // ---- prefetch next B into the other buffer (overlaps MMA) ----
        if (bn < 8) {
            const __half* Bn = wf + (size_t)(bn + 1) * DIM * DIM;
            const unsigned bnext = sBB0 + (unsigned)((bn + 1) & 1) * BSZ;
#pragma unroll
            for (int it = 0; it < 8; it++) {
                int id = tid + it * 256;
                int r  = id >> 4;
                int c  = id & 15;
                CP_ASYNC16(bnext + (unsigned)((r * AS + c * 8) * 2),
                           Bn + (size_t)r * DIM + c * 8);
            }
            CP_COMMIT();
        }

        // ---- MMA phase: 8 k-steps of 16 ----
        float acc[2][8][4];
#pragma unroll
        for (int mi = 0; mi < 2; mi++)
#pragma unroll
            for (int ni = 0; ni < 8; ni++)
#pragma unroll
                for (int q = 0; q < 4; q++) acc[mi][ni][q] = 0.0f;

#pragma unroll
        for (int ks = 0; ks < 8; ks++) {
            const unsigned kb = ks * 32;
            unsigned a[2][4];
#pragma unroll
            for (int mi = 0; mi < 2; mi++)
                LDSM4(a[mi], sAB + aoff + mi * (16 * AS * 2) + kb);
            unsigned b[8][2];
#pragma unroll
            for (int p = 0; p < 4; p++) {
                unsigned t[4];
                LDSM4(t, bsel + boff + p * (16 * AS * 2) + kb);
                b[2 * p][0] = t[0]; b[2 * p][1] = t[1];
                b[2 * p + 1][0] = t[2]; b[2 * p + 1][1] = t[3];
            }
#pragma unroll
            for (int ni = 0; ni < 8; ni++)
#pragma unroll
                for (int mi = 0; mi < 2; mi++)
                    MMA16816(acc[mi][ni], a[mi], b[ni]);
        }

        // ---- epilogue for this bn ----
#pragma unroll
        for (int mi = 0; mi < 2; mi++) {
            int r0 = row0 + wm * 32 + mi * 16 + grp;
#pragma unroll
            for (int ni = 0; ni < 8; ni++) {
                int col = wn * 64 + ni * 8 + 2 * tg;
                if (bn == 0) {
                    float b0 = bias[col], b1 = bias[col + 1];
                    if (r0 < nrows) {
                        float2 o = make_float2(acc[mi][ni][0] + b0, acc[mi][ni][1] + b1);
                        *(float2*)&outroot[(size_t)r0 * DIM + col] = o;
                    }
                    if (r0 + 8 < nrows) {
                        float2 o = make_float2(acc[mi][ni][2] + b0, acc[mi][ni][3] + b1);
                        *(float2*)&outroot[(size_t)(r0 + 8) * DIM + col] = o;
                    }
                } else {
                    int rel = bn - 1;
                    if (r0 < nrows) {
                        __half2 o = __floats2half2_rn(acc[mi][ni][0], acc[mi][ni][1]);
                        *(__half2*)&g_Yh[((size_t)r0 * NREL + rel) * DIM + col] = o;
                    }
                    if (r0 + 8 < nrows) {
                        __half2 o = __floats2half2_rn(acc[mi][ni][2], acc[mi][ni][3]);
                        *(__half2*)&g_Yh[((size_t)(r0 + 8) * NREL + rel) * DIM + col] = o;
                    }
                }
            }
        }

        if (bn < 8) CP_WAIT0();
        __syncthreads();
    }
}

// ---------------------------------------------------------------------------
// Owner-computes aggregation + fused relu/output-convert. One warp per dst.
//   tot = sum_r mean(Yh[src][r]) ; v = relu(in[dst] + tot)
//   tofp16 ? g_Af[dst] = (half)v : outf32[dst] = v
// ---------------------------------------------------------------------------
__global__ __launch_bounds__(256) void agg_kernel(
    const float* __restrict__ in, float* __restrict__ outf32,
    int n, int tofp16)
{
    int gw   = (blockIdx.x * 256 + threadIdx.x) >> 5;
    int lane = threadIdx.x & 31;
    if (gw >= n) return;
    const int dst  = gw;
    const int half = lane >> 4;
    const int hl   = lane & 15;

    int ov = 0;
    if (lane < 9) ov = g_off[dst * NREL + lane];

    float tot[8];
#pragma unroll
    for (int j = 0; j < 8; j++) tot[j] = 0.0f;

#pragma unroll
    for (int r = 0; r < NREL; r++) {
        int s0 = __shfl_sync(0xffffffffu, ov, r);
        int s1 = __shfl_sync(0xffffffffu, ov, r + 1);
        int c  = s1 - s0;
        if (c <= 0) continue;
        float acc[8];
#pragma unroll
        for (int j = 0; j < 8; j++) acc[j] = 0.0f;
        for (int i = s0 + half; i < s1; i += 2) {
            int src = g_esrc[i];
            const uint4 v = *(const uint4*)(g_Yh +
                (((size_t)src * NREL + r) << 7) + hl * 8);
            const __half2* h2 = reinterpret_cast<const __half2*>(&v);
#pragma unroll
            for (int j = 0; j < 4; j++) {
                float2 f = __half22float2(h2[j]);
                acc[2 * j]     += f.x;
                acc[2 * j + 1] += f.y;
            }
        }
        float s = 1.0f / (float)c;
#pragma unroll
        for (int j = 0; j < 8; j++) tot[j] += acc[j] * s;
    }

#pragma unroll
    for (int j = 0; j < 8; j++)
        tot[j] += __shfl_xor_sync(0xffffffffu, tot[j], 16);

    if (half == 0) {
        const float4 i0 = *(const float4*)(in + (size_t)dst * DIM + hl * 8);
        const float4 i1 = *(const float4*)(in + (size_t)dst * DIM + hl * 8 + 4);
        float v[8];
        v[0] = fmaxf(i0.x + tot[0], 0.f); v[1] = fmaxf(i0.y + tot[1], 0.f);
        v[2] = fmaxf(i0.z + tot[2], 0.f); v[3] = fmaxf(i0.w + tot[3], 0.f);
        v[4] = fmaxf(i1.x + tot[4], 0.f); v[5] = fmaxf(i1.y + tot[5], 0.f);
        v[6] = fmaxf(i1.z + tot[6], 0.f); v[7] = fmaxf(i1.w + tot[7], 0.f);
        if (tofp16) {
            uint4 u;
            __half2 h;
            h = __floats2half2_rn(v[0], v[1]); u.x = *reinterpret_cast<unsigned*>(&h);
            h = __floats2half2_rn(v[2], v[3]); u.y = *reinterpret_cast<unsigned*>(&h);
            h = __floats2half2_rn(v[4], v[5]); u.z = *reinterpret_cast<unsigned*>(&h);
            h = __floats2half2_rn(v[6], v[7]); u.w = *reinterpret_cast<unsigned*>(&h);
            *(uint4*)(g_Af + (size_t)dst * DIM + hl * 8) = u;
        } else {
            *(float4*)(outf32 + (size_t)dst * DIM + hl * 8) =
                make_float4(v[0], v[1], v[2], v[3]);
            *(float4*)(outf32 + (size_t)dst * DIM + hl * 8 + 4) =
                make_float4(v[4], v[5], v[6], v[7]);
        }
    }
}

// ---------------------------------------------------------------------------
// Launch
// ---------------------------------------------------------------------------
extern "C" void kernel_launch(void* const* d_in, const int* in_sizes, int n_in,
                              void* d_out, int out_size)
{
    const float* x   = (const float*)d_in[0];
    const int*   ei  = (const int*)d_in[1];  // [2,E] int32
    const int*   et  = (const int*)d_in[2];  // [E]   int32
    const float* rw1 = (const float*)d_in[3];
    const float* ro1 = (const float*)d_in[4];
    const float* b1  = (const float*)d_in[5];
    const float* rw2 = (const float*)d_in[6];
    const float* ro2 = (const float*)d_in[7];
    const float* b2  = (const float*)d_in[8];
    float* out = (float*)d_out;

    const int n = in_sizes[0] / DIM;
    const int e = in_sizes[2];

    float* hptr;
    cudaGetSymbolAddress((void**)&hptr, g_h);
    __half* wf;
    cudaGetSymbolAddress((void**)&wf, g_Wf);

    const int smem_bytes = 3 * 128 * AS * 2;   // A + 2x B = 104448
    static bool attr_done = false;
    if (!attr_done) {
        cudaFuncSetAttribute(gemm_bn_kernel,
                             cudaFuncAttributeMaxDynamicSharedMemorySize, smem_bytes);
        attr_done = true;
    }

    const int n8 = n * NREL;
    const int nscan = (n8 + 1023) / 1024;
    const int mtiles = (n + 127) / 128;
    const int nw = 9 * DIM * DIM;

    // conversions
    wconvert_kernel<<<(nw + 255) / 256, 256>>>(ro1, rw1, wf);
    wconvert_kernel<<<(nw + 255) / 256, 256>>>(ro2, rw2, wf + nw);
    convert_half_kernel<<<(n * 32 + 255) / 256, 256>>>(x, n * 32);

    // CSR build (shared by both layers)
    zero_cnt_kernel<<<(n8 / 4 + 255) / 256, 256>>>(n8 / 4);
    hist_kernel<<<(e + 255) / 256, 256>>>(ei, et, e);
    scan1_kernel<<<nscan, 256>>>(n8);
    scan2_kernel<<<1, 1024>>>(nscan);
    scan3_kernel<<<(n8 + 255) / 256, 256>>>(n8, e);
    sort_edges_kernel<<<(e + 255) / 256, 256>>>(ei, et, e);

    // layer 1: gemm -> h(root) + Yh ; agg fuses +mean, relu, fp16 -> g_Af
    gemm_bn_kernel<<<mtiles, 256, smem_bytes>>>(wf, b1, hptr, n);
    agg_kernel<<<(n * 32 + 255) / 256, 256>>>(hptr, nullptr, n, 1);

    // layer 2: gemm -> out(root) + Yh ; agg fuses +mean, relu -> out fp32
    gemm_bn_kernel<<<mtiles, 256, smem_bytes>>>(wf + nw, b2, out, n);
    agg_kernel<<<(n * 32 + 255) / 256, 256>>>(out, out, n, 0);
}

// round 13
// speedup vs baseline: 1.5371x; 1.3201x over previous
#include <cuda_runtime.h>
#include <cuda_fp16.h>
#include <cstdint>

#define NMAX 100000
#define DIM 128
#define NREL 8
#define KTOT 1152     // 9 * 128
#define AS2 72        // padded smem row stride (halfs) for BK=64 chunks

// Scratch (static device globals; runtime allocation is forbidden)
__device__ __half g_Az[(size_t)NMAX * KTOT];          // [N][9][128]: x | Z_1..Z_8 (fp16)
__device__ __half g_Af[(size_t)NMAX * DIM];           // fp16 activations (gather source)
__device__ __half g_Wf[2 * 9 * DIM * DIM];            // fp16 transposed [bn][n][k] weights
// CSR sort structures (shared by both layers)
__device__ int g_cnt[NMAX * NREL];
__device__ int g_off[NMAX * NREL + 1];
__device__ int g_cursor[NMAX * NREL];
__device__ int g_bsum[1024];
__device__ int g_esrc[640000];

// ---------------------------------------------------------------------------
// fp16 conversions
// ---------------------------------------------------------------------------
// x fp32 -> g_Af AND g_Az chunk 0
__global__ void convert_half_kernel(const float* __restrict__ src, int nelem4) {
    int i = blockIdx.x * blockDim.x + threadIdx.x;
    if (i >= nelem4) return;
    float4 v = ((const float4*)src)[i];
    __half2 h0 = __floats2half2_rn(v.x, v.y);
    __half2 h1 = __floats2half2_rn(v.z, v.w);
    uint2 packed = make_uint2(*reinterpret_cast<unsigned*>(&h0),
                              *reinterpret_cast<unsigned*>(&h1));
    ((uint2*)g_Af)[i] = packed;
    int row = i >> 5;
    ((uint2*)g_Az)[row * 288 + (i & 31)] = packed;   // 288 = 1152/4
}

// weights [k][n] fp32 -> transposed [bn][n][k] fp16
__global__ void wconvert_kernel(const float* __restrict__ root,
                                const float* __restrict__ rel,
                                __half* __restrict__ wf) {
    int i = blockIdx.x * blockDim.x + threadIdx.x;
    if (i >= 9 * DIM * DIM) return;
    int bn = i >> 14;
    int t  = i & 16383;
    int n  = t >> 7;
    int k  = t & 127;
    float w = bn ? rel[(size_t)(bn - 1) * DIM * DIM + k * DIM + n] : root[k * DIM + n];
    wf[i] = __float2half_rn(w);
}

// ---------------------------------------------------------------------------
// CSR build: histogram -> 2-level exclusive scan -> counting sort of src ids
// ---------------------------------------------------------------------------
__global__ void zero_cnt_kernel(int n8v4) {
    int i = blockIdx.x * blockDim.x + threadIdx.x;
    if (i < n8v4) ((int4*)g_cnt)[i] = make_int4(0, 0, 0, 0);
}

__global__ void hist_kernel(const int* __restrict__ ei,
                            const int* __restrict__ et, int e) {
    int i = blockIdx.x * blockDim.x + threadIdx.x;
    if (i >= e) return;
    atomicAdd(&g_cnt[ei[e + i] * NREL + et[i]], 1);
}

__global__ void scan1_kernel(int n8) {
    __shared__ int sm[256];
    int t = threadIdx.x;
    int base = blockIdx.x * 1024 + t * 4;
    int v0 = 0, v1 = 0, v2 = 0, v3 = 0;
    if (base + 0 < n8) v0 = g_cnt[base + 0];
    if (base + 1 < n8) v1 = g_cnt[base + 1];
    if (base + 2 < n8) v2 = g_cnt[base + 2];
    if (base + 3 < n8) v3 = g_cnt[base + 3];
    int tsum = v0 + v1 + v2 + v3;
    sm[t] = tsum;
    __syncthreads();
#pragma unroll
    for (int d = 1; d < 256; d <<= 1) {
        int x = (t >= d) ? sm[t - d] : 0;
        __syncthreads();
        sm[t] += x;
        __syncthreads();
    }
    int run = sm[t] - tsum;
    if (base + 0 < n8) { g_off[base + 0] = run; run += v0; }
    if (base + 1 < n8) { g_off[base + 1] = run; run += v1; }
    if (base + 2 < n8) { g_off[base + 2] = run; run += v2; }
    if (base + 3 < n8) { g_off[base + 3] = run; }
    if (t == 255) g_bsum[blockIdx.x] = sm[255];
}

__global__ void scan2_kernel(int nb) {
    __shared__ int sm[1024];
    int t = threadIdx.x;
    int v = (t < nb) ? g_bsum[t] : 0;
    sm[t] = v;
    __syncthreads();
#pragma unroll
    for (int d = 1; d < 1024; d <<= 1) {
        int x = (t >= d) ? sm[t - d] : 0;
        __syncthreads();
        sm[t] += x;
        __syncthreads();
    }
    if (t < nb) g_bsum[t] = sm[t] - v;
}

__global__ void scan3_kernel(int n8, int e) {
    int i = blockIdx.x * blockDim.x + threadIdx.x;
    if (i < n8) {
        int v = g_off[i] + g_bsum[i >> 10];
        g_off[i] = v;
        g_cursor[i] = v;
    }
    if (i == 0) g_off[n8] = e;
}

__global__ void sort_edges_kernel(const int* __restrict__ ei,
                                  const int* __restrict__ et, int e) {
    int i = blockIdx.x * blockDim.x + threadIdx.x;
    if (i >= e) return;
    int bin = ei[e + i] * NREL + et[i];
    int pos = atomicAdd(&g_cursor[bin], 1);
    g_esrc[pos] = ei[i];
}

// ---------------------------------------------------------------------------
// Aggregate-first: Z[dst][r] = mean_{edges in bin(dst,r)} g_Af[src]  (fp16)
// One warp per dst. Gathers hit the L2-resident 25.6MB g_Af.
// Writes g_Az chunks 1..8 (always, zeros for empty bins).
// ---------------------------------------------------------------------------
__global__ __launch_bounds__(256) void aggz_kernel(int n)
{
    int gw   = (blockIdx.x * 256 + threadIdx.x) >> 5;
    int lane = threadIdx.x & 31;
    if (gw >= n) return;
    const int dst  = gw;
    const int half = lane >> 4;
    const int hl   = lane & 15;

    int ov = 0;
    if (lane < 9) ov = g_off[dst * NREL + lane];

#pragma unroll
    for (int r = 0; r < NREL; r++) {
        int s0 = __shfl_sync(0xffffffffu, ov, r);
        int s1 = __shfl_sync(0xffffffffu, ov, r + 1);
        int c  = s1 - s0;
        float acc[8];
#pragma unroll
        for (int j = 0; j < 8; j++) acc[j] = 0.0f;
        for (int i = s0 + half; i < s1; i += 2) {
            int src = g_esrc[i];
            const uint4 v = *(const uint4*)(g_Af + ((size_t)src << 7) + hl * 8);
            const __half2* h2 = reinterpret_cast<const __half2*>(&v);
#pragma unroll
            for (int j = 0; j < 4; j++) {
                float2 f = __half22float2(h2[j]);
                acc[2 * j]     += f.x;
                acc[2 * j + 1] += f.y;
            }
        }
#pragma unroll
        for (int j = 0; j < 8; j++)
            acc[j] += __shfl_xor_sync(0xffffffffu, acc[j], 16);
        if (half == 0) {
            float inv = (c > 0) ? 1.0f / (float)c : 0.0f;
            uint4 u;
            __half2 h;
            h = __floats2half2_rn(acc[0] * inv, acc[1] * inv);
            u.x = *reinterpret_cast<unsigned*>(&h);
            h = __floats2half2_rn(acc[2] * inv, acc[3] * inv);
            u.y = *reinterpret_cast<unsigned*>(&h);
            h = __floats2half2_rn(acc[4] * inv, acc[5] * inv);
            u.z = *reinterpret_cast<unsigned*>(&h);
            h = __floats2half2_rn(acc[6] * inv, acc[7] * inv);
            u.w = *reinterpret_cast<unsigned*>(&h);
            *(uint4*)(g_Az + (size_t)dst * KTOT + (r + 1) * DIM + hl * 8) = u;
        }
    }
}

// ---------------------------------------------------------------------------
// Pipelined K=1152 GEMM (mma m16n8k16 fp16, fp32 accum):
//   out[128-tile] = g_Az[tile] @ Wstack + bias, then relu.
//   BK=64, 2-stage cp.async double buffer (A and B). 256 thr = 8 warps (4x2).
//   mode 0: write fp16 -> g_Af and g_Az chunk0 (next layer). mode 1: fp32 out.
// ---------------------------------------------------------------------------
#define MMA16816(d, a, b)                                                  \
    asm volatile(                                                          \
        "mma.sync.aligned.m16n8k16.row.col.f32.f16.f16.f32 "               \
        "{%0,%1,%2,%3},{%4,%5,%6,%7},{%8,%9},{%0,%1,%2,%3};"               \
        : "+f"(d[0]), "+f"(d[1]), "+f"(d[2]), "+f"(d[3])                   \
        : "r"(a[0]), "r"(a[1]), "r"(a[2]), "r"(a[3]), "r"(b[0]), "r"(b[1]))

#define LDSM4(R, ADDR)                                                     \
    asm volatile("ldmatrix.sync.aligned.m8n8.x4.shared.b16 "               \
                 "{%0,%1,%2,%3}, [%4];"                                    \
                 : "=r"(R[0]), "=r"(R[1]), "=r"(R[2]), "=r"(R[3])          \
                 : "r"(ADDR))

#define CP_ASYNC16(dst, src)                                               \
    asm volatile("cp.async.ca.shared.global [%0], [%1], 16;"               \
                 :: "r"(dst), "l"(src) : "memory")
#define CP_COMMIT()  asm volatile("cp.async.commit_group;" ::: "memory")
#define CP_WAIT(N)   asm volatile("cp.async.wait_group %0;" :: "n"(N) : "memory")

__global__ __launch_bounds__(256) void gemm_k_kernel(
    const __half* __restrict__ wf,   // layer base [9][128][128] (n,k)
    const float* __restrict__ bias,
    float* __restrict__ out32, int nrows, int mode)
{
    extern __shared__ __half smem[];
    const int row0 = blockIdx.x * 128;
    const int tid  = threadIdx.x;
    const int lane = tid & 31;
    const int warp = tid >> 5;
    const int wm   = warp & 3;
    const int wn   = warp >> 2;
    const int grp  = lane >> 2;
    const int tg   = lane & 3;

    const unsigned sBase = (unsigned)__cvta_generic_to_shared(smem);
    const unsigned BUF = 128 * AS2 * 2;          // 18432 B
    const unsigned sA0 = sBase, sB0 = sBase + 2 * BUF;

    const unsigned aoff = (unsigned)(((wm * 32 + (lane & 15)) * AS2 +
                                      ((lane >> 4) << 3)) * 2);
    const unsigned boff = (unsigned)(((wn * 64 + ((lane >> 4) << 3) + (lane & 7)) * AS2 +
                                      (((lane >> 3) & 1) << 3)) * 2);

    auto stage = [&](int kc) {
        const unsigned abuf = sA0 + (unsigned)(kc & 1) * BUF;
        const unsigned bbuf = sB0 + (unsigned)(kc & 1) * BUF;
        const int bn   = kc >> 1;
        const int koff = (kc & 1) * 64;
        const __half* Bsrc = wf + (size_t)bn * DIM * DIM + koff;
#pragma unroll
        for (int it = 0; it < 4; it++) {
            int id = tid + it * 256;
            int r  = id >> 3;       // 0..127
            int c  = id & 7;        // 16B chunk within 128B
            int gr = row0 + r;
            unsigned ad = abuf + (unsigned)((r * AS2 + c * 8) * 2);
            if (gr < nrows) {
                CP_ASYNC16(ad, g_Az + (size_t)gr * KTOT + kc * 64 + c * 8);
            } else {
                asm volatile("st.shared.v4.b32 [%0], {%1,%1,%1,%1};"
                             :: "r"(ad), "r"(0u) : "memory");
            }
            CP_ASYNC16(bbuf + (unsigned)((r * AS2 + c * 8) * 2),
                       Bsrc + (size_t)r * DIM + c * 8);
        }
        CP_COMMIT();
    };

    float acc[2][8][4];
#pragma unroll
    for (int mi = 0; mi < 2; mi++)
#pragma unroll
        for (int ni = 0; ni < 8; ni++)
#pragma unroll
            for (int q = 0; q < 4; q++) acc[mi][ni][q] = 0.0f;

    stage(0);
    for (int kc = 0; kc < 18; kc++) {
        if (kc < 17) {
            stage(kc + 1);
            CP_WAIT(1);
        } else {
            CP_WAIT(0);
        }
        __syncthreads();

        const unsigned abuf = sA0 + (unsigned)(kc & 1) * BUF;
        const unsigned bbuf = sB0 + (unsigned)(kc & 1) * BUF;
#pragma unroll
        for (int ks = 0; ks < 4; ks++) {
            const unsigned kb = ks * 32;
            unsigned a[2][4];
#pragma unroll
            for (int mi = 0; mi < 2; mi++)
                LDSM4(a[mi], abuf + aoff + mi * (16 * AS2 * 2) + kb);
            unsigned b[8][2];
#pragma unroll
            for (int p = 0; p < 4; p++) {
                unsigned t[4];
                LDSM4(t, bbuf + boff + p * (16 * AS2 * 2) + kb);
                b[2 * p][0] = t[0]; b[2 * p][1] = t[1];
                b[2 * p + 1][0] = t[2]; b[2 * p + 1][1] = t[3];
            }
#pragma unroll
            for (int ni = 0; ni < 8; ni++)
#pragma unroll
                for (int mi = 0; mi < 2; mi++)
                    MMA16816(acc[mi][ni], a[mi], b[ni]);
        }
        __syncthreads();   // all warps done with this buffer before restage
    }

    // ---- epilogue: relu(acc + bias) ----
#pragma unroll
    for (int mi = 0; mi < 2; mi++) {
        int r0 = row0 + wm * 32 + mi * 16 + grp;
#pragma unroll
        for (int ni = 0; ni < 8; ni++) {
            int col = wn * 64 + ni * 8 + 2 * tg;
            float b0 = bias[col], b1 = bias[col + 1];
            float v00 = fmaxf(acc[mi][ni][0] + b0, 0.f);
            float v01 = fmaxf(acc[mi][ni][1] + b1, 0.f);
            float v10 = fmaxf(acc[mi][ni][2] + b0, 0.f);
            float v11 = fmaxf(acc[mi][ni][3] + b1, 0.f);
            if (mode == 0) {
                if (r0 < nrows) {
                    __half2 h = __floats2half2_rn(v00, v01);
                    unsigned u = *reinterpret_cast<unsigned*>(&h);
                    *(unsigned*)(g_Af + ((size_t)r0 << 7) + col) = u;
                    *(unsigned*)(g_Az + (size_t)r0 * KTOT + col) = u;
                }
                if (r0 + 8 < nrows) {
                    __half2 h = __floats2half2_rn(v10, v11);
                    unsigned u = *reinterpret_cast<unsigned*>(&h);
                    *(unsigned*)(g_Af + ((size_t)(r0 + 8) << 7) + col) = u;
                    *(unsigned*)(g_Az + (size_t)(r0 + 8) * KTOT + col) = u;
                }
            } else {
                if (r0 < nrows)
                    *(float2*)&out32[(size_t)r0 * DIM + col] = make_float2(v00, v01);
                if (r0 + 8 < nrows)
                    *(float2*)&out32[(size_t)(r0 + 8) * DIM + col] = make_float2(v10, v11);
            }
        }
    }
}

// ---------------------------------------------------------------------------
// Launch
// ---------------------------------------------------------------------------
extern "C" void kernel_launch(void* const* d_in, const int* in_sizes, int n_in,
                              void* d_out, int out_size)
{
    const float* x   = (const float*)d_in[0];
    const int*   ei  = (const int*)d_in[1];  // [2,E] int32
    const int*   et  = (const int*)d_in[2];  // [E]   int32
    const float* rw1 = (const float*)d_in[3];
    const float* ro1 = (const float*)d_in[4];
    const float* b1  = (const float*)d_in[5];
    const float* rw2 = (const float*)d_in[6];
    const float* ro2 = (const float*)d_in[7];
    const float* b2  = (const float*)d_in[8];
    float* out = (float*)d_out;

    const int n = in_sizes[0] / DIM;
    const int e = in_sizes[2];

    __half* wf;
    cudaGetSymbolAddress((void**)&wf, g_Wf);

    const int smem_bytes = 4 * 128 * AS2 * 2;   // 73728
    static bool attr_done = false;
    if (!attr_done) {
        cudaFuncSetAttribute(gemm_k_kernel,
                             cudaFuncAttributeMaxDynamicSharedMemorySize, smem_bytes);
        attr_done = true;
    }

    const int n8 = n * NREL;
    const int nscan = (n8 + 1023) / 1024;
    const int mtiles = (n + 127) / 128;
    const int nw = 9 * DIM * DIM;

    // conversions
    wconvert_kernel<<<(nw + 255) / 256, 256>>>(ro1, rw1, wf);
    wconvert_kernel<<<(nw + 255) / 256, 256>>>(ro2, rw2, wf + nw);
    convert_half_kernel<<<(n * 32 + 255) / 256, 256>>>(x, n * 32);

    // CSR build (shared by both layers)
    zero_cnt_kernel<<<(n8 / 4 + 255) / 256, 256>>>(n8 / 4);
    hist_kernel<<<(e + 255) / 256, 256>>>(ei, et, e);
    scan1_kernel<<<nscan, 256>>>(n8);
    scan2_kernel<<<1, 1024>>>(nscan);
    scan3_kernel<<<(n8 + 255) / 256, 256>>>(n8, e);
    sort_edges_kernel<<<(e + 255) / 256, 256>>>(ei, et, e);

    // layer 1: aggregate x into Z, then K=1152 GEMM -> fp16 activations
    aggz_kernel<<<(n * 32 + 255) / 256, 256>>>(n);
    gemm_k_kernel<<<mtiles, 256, smem_bytes>>>(wf, b1, nullptr, n, 0);

    // layer 2: aggregate h into Z, then GEMM -> fp32 out (relu fused)
    aggz_kernel<<<(n * 32 + 255) / 256, 256>>>(n);
    gemm_k_kernel<<<mtiles, 256, smem_bytes>>>(wf + nw, b2, out, n, 1);
}